// round 6
// baseline (speedup 1.0000x reference)
#include <cuda_runtime.h>
#include <math.h>

#define BB   512
#define SS   1024
#define KK   50
#define MM   50
#define VV   200
#define AA   64
#define TWOA 128
#define NB   4
#define NBLK (BB / NB)     // 128 CTAs
#define NTHR 800           // 25 warps
#define WPAD 52            // s_w row stride (16B-aligned float4 rows)

// ---- static shared memory layout (floats) ----
#define OFF_Q    0                      // [2][200] double-buffered q
#define OFF_AT   (OFF_Q   + 400)        // [2][256] double-buffered att (b*64+j)
#define OFF_RC   (OFF_AT  + 512)        // [256]  rc (b*64+a)
#define OFF_CK   (OFF_RC  + 256)        // [200]
#define OFF_W    (OFF_CK  + 200)        // [4*52]
#define OFF_R    (OFF_W   + 4*WPAD)     // [800]
#define OFF_ER   (OFF_R   + 800)        // [800] raw erase dots
#define OFF_AR   (OFF_ER  + 800)        // [800] raw add dots
#define OFF_WCT  (OFF_AR  + 800)        // [2500] Wc transposed [j][k]
#define OFF_KMT  (OFF_WCT + 2500)       // [2500] km transposed [k][m]
#define OFF_BC   (OFF_KMT + 2500)       // [50]
#define OFF_BR   (OFF_BC  + 52)         // [64]
#define OFF_BE   (OFF_BR  + 64)         // [200]
#define OFF_BA   (OFF_BE  + 200)        // [200]
#define SMEM_FLOATS (OFF_BA + 200)      // ~9.5K floats (~38 KB, static)

// Output offsets (floats) in concatenated flat output
#define OUT_RC  0ULL                                        // (B,S,A)
#define OUT_MEM ((unsigned long long)BB * SS * AA)          // (B,M,V)
#define OUT_W   (OUT_MEM + (unsigned long long)BB*MM*VV)    // (B,S,M)

// 4-value cross-warp reduction: lanes enter with partials of 4 independent
// sums; every lane exits with the full sum of index (lane>>3)&3.
__device__ __forceinline__ float reduce4(float a0, float a1, float a2, float a3,
                                         int lane)
{
    if (lane & 16) { float t = a0; a0 = a2; a2 = t; t = a1; a1 = a3; a3 = t; }
    a0 += __shfl_xor_sync(0xffffffffu, a2, 16);
    a1 += __shfl_xor_sync(0xffffffffu, a3, 16);
    if (lane & 8)  { float t = a0; a0 = a1; a1 = t; }
    a0 += __shfl_xor_sync(0xffffffffu, a1, 8);
    a0 += __shfl_xor_sync(0xffffffffu, a0, 4);
    a0 += __shfl_xor_sync(0xffffffffu, a0, 2);
    a0 += __shfl_xor_sync(0xffffffffu, a0, 1);
    return a0;
}

__device__ __forceinline__ float dot4(float4 a, float4 b, float acc)
{
    acc = fmaf(a.x, b.x, acc);
    acc = fmaf(a.y, b.y, acc);
    acc = fmaf(a.z, b.z, acc);
    acc = fmaf(a.w, b.w, acc);
    return acc;
}

__global__ __launch_bounds__(NTHR, 1)
void agm_kernel(const float* __restrict__ q_emb,   // (B,S,K)
                const float* __restrict__ att,     // (B,S,A)
                const float* __restrict__ vmem,    // (B,M,V)
                const float* __restrict__ km,      // (M,K)
                const float* __restrict__ Wc,      // (K,K)
                const float* __restrict__ bc,      // (K)
                const float* __restrict__ Wr,      // (A,V)
                const float* __restrict__ br,      // (A)
                const float* __restrict__ We,      // (V,2A)
                const float* __restrict__ be,      // (V)
                const float* __restrict__ Wa,      // (V,2A)
                const float* __restrict__ ba,      // (V)
                float* __restrict__ out)
{
    __shared__ float sh[SMEM_FLOATS];

    const int tid  = threadIdx.x;
    const int lane = tid & 31;
    const int wid  = tid >> 5;
    const int gb0  = blockIdx.x * NB;

    const int bcol = tid / VV;       // owned batch
    const int vcol = tid % VV;       // owned memory column

    // ---- per-thread memory state: mem[m] = value_memory[b][m][vcol] ----
    float mem[MM];
    {
        const float* src = vmem + (size_t)(gb0 + bcol) * (MM * VV) + vcol;
        #pragma unroll
        for (int m = 0; m < MM; ++m) mem[m] = src[m * VV];
    }

    // ---- one-time setup: transposed small weights + biases + t=0 inputs ----
    for (int p = tid; p < KK * KK; p += NTHR) {          // WcT[j][k] = Wc[k][j]
        int j = p / KK, k = p % KK;
        sh[OFF_WCT + j * KK + k] = Wc[k * KK + j];
    }
    for (int p = tid; p < MM * KK; p += NTHR) {          // kmT[k][m] = km[m][k]
        int k = p / MM, m = p % MM;
        sh[OFF_KMT + k * MM + m] = km[m * KK + k];
    }
    for (int p = tid; p < KK; p += NTHR) sh[OFF_BC + p] = bc[p];
    for (int p = tid; p < AA; p += NTHR) sh[OFF_BR + p] = br[p];
    for (int p = tid; p < VV; p += NTHR) { sh[OFF_BE + p] = be[p]; sh[OFF_BA + p] = ba[p]; }
    if (tid < NB * KK) {                                  // q[t=0]
        sh[OFF_Q + tid] = q_emb[((size_t)(gb0 + tid / KK) * SS) * KK + tid % KK];
    } else if (tid < NB * KK + NB * AA) {                 // att[t=0]
        int i = tid - NB * KK;
        sh[OFF_AT + i] = att[((size_t)(gb0 + (i >> 6)) * SS) * AA + (i & 63)];
    }
    __syncthreads();

    for (int t = 0; t < SS; ++t) {
        const int cur = t & 1, nxt = cur ^ 1;
        const int tpf = (t + 1 < SS) ? t + 1 : SS - 1;

        // ---- prefetch issue for t+1 (store deferred to loop bottom) ----
        float pf = 0.f;
        if (tid < NB * KK) {
            pf = q_emb[((size_t)(gb0 + tid / KK) * SS + tpf) * KK + tid % KK];
        } else if (tid < NB * KK + NB * AA) {
            int i = tid - NB * KK;
            pf = att[((size_t)(gb0 + (i >> 6)) * SS + tpf) * AA + (i & 63)];
        }

        // ---- B: ck = tanh(q @ Wc^T + bc) ----
        if (tid < NB * KK) {
            int b = tid / KK, k = tid % KK;
            const float* wc = sh + OFF_WCT + k;           // column k of WcT
            const float* qb = sh + OFF_Q + cur * (NB * KK) + b * KK;
            float acc = sh[OFF_BC + k];
            #pragma unroll
            for (int j = 0; j < KK; ++j) acc = fmaf(wc[j * KK], qb[j], acc);
            float e = __expf(2.f * acc);
            sh[OFF_CK + b * KK + k] = 1.f - 2.f / (e + 1.f);  // tanh, inf-safe
        }
        __syncthreads();

        // ---- C: logits = ck @ km^T ----
        if (tid < NB * MM) {
            int b = tid / MM, m = tid % MM;
            const float* kc  = sh + OFF_KMT + m;          // column m of kmT
            const float* ckb = sh + OFF_CK + b * KK;
            float acc = 0.f;
            #pragma unroll
            for (int k = 0; k < KK; ++k) acc = fmaf(kc[k * MM], ckb[k], acc);
            sh[OFF_W + b * WPAD + m] = acc;
        }
        __syncthreads();

        // ---- D: softmax over M=50, one warp per batch ----
        if (wid < NB) {
            float* wb = sh + OFF_W + wid * WPAD;
            float x0 = wb[lane];
            float x1 = (lane + 32 < MM) ? wb[lane + 32] : -INFINITY;
            float mx = fmaxf(x0, x1);
            #pragma unroll
            for (int o = 16; o > 0; o >>= 1)
                mx = fmaxf(mx, __shfl_xor_sync(0xffffffffu, mx, o));
            float e0 = __expf(x0 - mx);
            float e1 = (lane + 32 < MM) ? __expf(x1 - mx) : 0.f;
            float s = e0 + e1;
            #pragma unroll
            for (int o = 16; o > 0; o >>= 1)
                s += __shfl_xor_sync(0xffffffffu, s, o);
            float inv = 1.f / s;
            wb[lane] = e0 * inv;
            if (lane + 32 < MM) wb[lane + 32] = e1 * inv;
        }
        __syncthreads();

        // ---- E: r[b][v] = sum_m w[b][m] * mem[m]  (mem in regs, w broadcast) ----
        {
            const float4* w4 = (const float4*)(sh + OFF_W + bcol * WPAD);
            float acc = 0.f;
            #pragma unroll
            for (int i = 0; i < 12; ++i) {
                float4 ww = w4[i];
                acc = fmaf(ww.x, mem[4 * i + 0], acc);
                acc = fmaf(ww.y, mem[4 * i + 1], acc);
                acc = fmaf(ww.z, mem[4 * i + 2], acc);
                acc = fmaf(ww.w, mem[4 * i + 3], acc);
            }
            float4 wl = w4[12];
            acc = fmaf(wl.x, mem[48], acc);
            acc = fmaf(wl.y, mem[49], acc);
            sh[OFF_R + bcol * VV + vcol] = acc;
        }
        __syncthreads();

        // ---- F: rc[b][a] = r[b] . Wr[a] + br[a]  (warp per row, coalesced) ----
        for (int a = wid; a < AA; a += 25) {
            const float4* wr4 = (const float4*)(Wr + a * VV);
            bool l2 = (lane < 18);
            float4 x = wr4[lane];                                       // v = 4l..4l+3
            float4 y = l2 ? wr4[32 + lane] : make_float4(0, 0, 0, 0);   // v = 128+4l..
            float acc[NB];
            #pragma unroll
            for (int b = 0; b < NB; ++b) {
                const float4* r4 = (const float4*)(sh + OFF_R + b * VV);
                float4 ra = r4[lane];
                float4 rb = l2 ? r4[32 + lane] : make_float4(0, 0, 0, 0);
                acc[b] = dot4(y, rb, dot4(x, ra, 0.f));
            }
            float s4 = reduce4(acc[0], acc[1], acc[2], acc[3], lane);
            if (!(lane & 7)) {
                int b = lane >> 3;
                sh[OFF_RC + b * AA + a] = s4 + sh[OFF_BR + a];
            }
        }
        __syncthreads();

        // ---- outputs for step t (coalesced, overlaps gates) ----
        if (tid < NB * AA) {
            int b = tid >> 6, a = tid & 63;
            out[OUT_RC + ((size_t)(gb0 + b) * SS + t) * AA + a] = sh[OFF_RC + tid];
        } else if (tid < NB * AA + NB * MM) {
            int i = tid - NB * AA;
            int b = i / MM, m = i % MM;
            out[OUT_W + ((size_t)(gb0 + b) * SS + t) * MM + m] = sh[OFF_W + b * WPAD + m];
        }

        // ---- G: gate matvecs (warp-per-row, wi in lane regs) ----
        if (t < SS - 1) {
            float4 wi0, wi1, wi2, wi3;
            {
                const float4* at4 = (const float4*)(sh + OFF_AT + cur * (NB * AA));
                const float4* rc4 = (const float4*)(sh + OFF_RC);
                int lo = lane & 15;
                wi0 = (lane < 16) ? at4[0 * 16 + lo] : rc4[0 * 16 + lo];
                wi1 = (lane < 16) ? at4[1 * 16 + lo] : rc4[1 * 16 + lo];
                wi2 = (lane < 16) ? at4[2 * 16 + lo] : rc4[2 * 16 + lo];
                wi3 = (lane < 16) ? at4[3 * 16 + lo] : rc4[3 * 16 + lo];
            }
            // pass 1: erase dots (We)
            #pragma unroll
            for (int r8 = 0; r8 < 8; ++r8) {
                int v = wid + 25 * r8;
                float4 wv = ((const float4*)(We + v * TWOA))[lane];  // one 512B row/warp
                float a0 = dot4(wv, wi0, 0.f);
                float a1 = dot4(wv, wi1, 0.f);
                float a2 = dot4(wv, wi2, 0.f);
                float a3 = dot4(wv, wi3, 0.f);
                float s4 = reduce4(a0, a1, a2, a3, lane);
                if (!(lane & 7)) sh[OFF_ER + (lane >> 3) * VV + v] = s4;
            }
            // pass 2: add dots (Wa)
            #pragma unroll
            for (int r8 = 0; r8 < 8; ++r8) {
                int v = wid + 25 * r8;
                float4 wv = ((const float4*)(Wa + v * TWOA))[lane];
                float a0 = dot4(wv, wi0, 0.f);
                float a1 = dot4(wv, wi1, 0.f);
                float a2 = dot4(wv, wi2, 0.f);
                float a3 = dot4(wv, wi3, 0.f);
                float s4 = reduce4(a0, a1, a2, a3, lane);
                if (!(lane & 7)) sh[OFF_AR + (lane >> 3) * VV + v] = s4;
            }
        }
        __syncthreads();

        // ---- H: nonlinearities + in-register memory update ----
        if (t < SS - 1) {
            float re = sh[OFF_ER + bcol * VV + vcol] + sh[OFF_BE + vcol];
            float ra = sh[OFF_AR + bcol * VV + vcol] + sh[OFF_BA + vcol];
            float er = 1.f / (1.f + __expf(-re));          // sigmoid
            float ea = __expf(2.f * ra);
            float ad = 1.f - 2.f / (ea + 1.f);             // tanh, inf-safe

            const float4* w4 = (const float4*)(sh + OFF_W + bcol * WPAD);
            #pragma unroll
            for (int i = 0; i < 12; ++i) {
                float4 ww = w4[i];
                mem[4*i+0] = fmaf(ww.x, fmaf(-er, mem[4*i+0], ad), mem[4*i+0]);
                mem[4*i+1] = fmaf(ww.y, fmaf(-er, mem[4*i+1], ad), mem[4*i+1]);
                mem[4*i+2] = fmaf(ww.z, fmaf(-er, mem[4*i+2], ad), mem[4*i+2]);
                mem[4*i+3] = fmaf(ww.w, fmaf(-er, mem[4*i+3], ad), mem[4*i+3]);
            }
            float4 wl = w4[12];
            mem[48] = fmaf(wl.x, fmaf(-er, mem[48], ad), mem[48]);
            mem[49] = fmaf(wl.y, fmaf(-er, mem[49], ad), mem[49]);
        }

        // ---- prefetch store into next buffers ----
        if (tid < NB * KK) {
            sh[OFF_Q + nxt * (NB * KK) + tid] = pf;
        } else if (tid < NB * KK + NB * AA) {
            sh[OFF_AT + nxt * (NB * AA) + (tid - NB * KK)] = pf;
        }
        __syncthreads();
    }

    // ---- final memory state (coalesced: lanes over v) ----
    {
        float* dst = out + OUT_MEM + (size_t)(gb0 + bcol) * (MM * VV) + vcol;
        #pragma unroll
        for (int m = 0; m < MM; ++m) dst[m * VV] = mem[m];
    }
}

extern "C" void kernel_launch(void* const* d_in, const int* in_sizes, int n_in,
                              void* d_out, int out_size)
{
    (void)in_sizes; (void)n_in; (void)out_size;
    agm_kernel<<<NBLK, NTHR>>>((const float*)d_in[0], (const float*)d_in[1],
                               (const float*)d_in[2], (const float*)d_in[3],
                               (const float*)d_in[4], (const float*)d_in[5],
                               (const float*)d_in[6], (const float*)d_in[7],
                               (const float*)d_in[8], (const float*)d_in[9],
                               (const float*)d_in[10], (const float*)d_in[11],
                               (float*)d_out);
}

// round 7
// speedup vs baseline: 1.1015x; 1.1015x over previous
#include <cuda_runtime.h>
#include <math.h>

#define BB   512
#define SS   1024
#define KK   50
#define MM   50
#define VV   200
#define AA   64
#define TWOA 128
#define NB   4
#define NBLK (BB / NB)     // 128 CTAs
#define NTHR 800           // 25 warps

// ---- kernel2 dynamic shared layout (float offsets, all 16B aligned) ----
#define OFF_WE  0                        // 200*128 = 25600 (We rows, contiguous)
#define OFF_WR  (OFF_WE + VV*TWOA)       // 64*208 = 13312 (Wr rows padded to 52 f4)
#define OFF_W   (OFF_WR + AA*208)        // 2*4*52 = 416 (double-buffered w)
#define OFF_AT  (OFF_W  + 2*NB*52)       // 2*256 = 512
#define OFF_RC  (OFF_AT + 2*NB*AA)       // 256
#define OFF_R   (OFF_RC + NB*AA)         // 800
#define OFF_ER  (OFF_R  + NB*VV)         // 800
#define OFF_AR  (OFF_ER + NB*VV)         // 800
#define OFF_BR  (OFF_AR + NB*VV)         // 64
#define OFF_BE  (OFF_BR + AA)            // 200
#define OFF_BA  (OFF_BE + VV)            // 200
#define SMEM2_FLOATS (OFF_BA + VV)
#define SMEM2_BYTES  (SMEM2_FLOATS * 4)  // ~171.8 KB

// Output offsets (floats) in concatenated flat output
#define OUT_RC  0ULL                                        // (B,S,A)
#define OUT_MEM ((unsigned long long)BB * SS * AA)          // (B,M,V)
#define OUT_W   (OUT_MEM + (unsigned long long)BB*MM*VV)    // (B,S,M)

// ============================================================================
// Kernel 1: precompute attention weights w[b,t,m] for ALL (b,t) in parallel.
//   w = softmax( tanh(q @ Wc^T + bc) @ km^T )   — independent of memory state.
// Writes directly into the memory_weights output region.
// ============================================================================
#define K1_GROUPS 8       // (b,t) pairs per block
#define K1_THREADS 512    // 64 threads per group
#define K1_ITERS  4       // pairs per block = 32
#define K1_GRID   ((BB * SS) / (K1_GROUPS * K1_ITERS))   // 16384

__global__ __launch_bounds__(K1_THREADS)
void agm_weights_kernel(const float* __restrict__ q_emb,  // (B,S,K)
                        const float* __restrict__ km,     // (M,K)
                        const float* __restrict__ Wc,     // (K,K)
                        const float* __restrict__ bc,     // (K)
                        float* __restrict__ out)
{
    __shared__ float s_WcT[KK * KK];   // [j][k]
    __shared__ float s_kmT[KK * MM];   // [k][m]
    __shared__ float s_bc[KK];
    __shared__ float s_q [K1_GROUPS][52];
    __shared__ float s_ck[K1_GROUPS][52];
    __shared__ float s_lg[K1_GROUPS][52];

    const int tid = threadIdx.x;
    const int g   = tid >> 6;         // group 0..7
    const int lt  = tid & 63;         // thread-in-group
    const int lane = tid & 31;

    for (int p = tid; p < KK * KK; p += K1_THREADS) {
        int j = p / KK, k = p % KK;
        s_WcT[j * KK + k] = Wc[k * KK + j];
    }
    for (int p = tid; p < MM * KK; p += K1_THREADS) {
        int k = p / MM, m = p % MM;
        s_kmT[k * MM + m] = km[m * KK + k];
    }
    for (int p = tid; p < KK; p += K1_THREADS) s_bc[p] = bc[p];
    __syncthreads();

    for (int it = 0; it < K1_ITERS; ++it) {
        const int p = (blockIdx.x * K1_ITERS + it) * K1_GROUPS + g;  // (b,t) id
        // p = b*SS + t directly indexes (b,t,·) rows

        if (lt < KK) s_q[g][lt] = q_emb[(size_t)p * KK + lt];
        __syncthreads();

        if (lt < KK) {                      // ck[k]
            const int k = lt;
            float a0 = s_bc[k], a1 = 0.f, a2 = 0.f, a3 = 0.f;
            #pragma unroll
            for (int j = 0; j < 48; j += 4) {
                a0 = fmaf(s_WcT[(j+0) * KK + k], s_q[g][j+0], a0);
                a1 = fmaf(s_WcT[(j+1) * KK + k], s_q[g][j+1], a1);
                a2 = fmaf(s_WcT[(j+2) * KK + k], s_q[g][j+2], a2);
                a3 = fmaf(s_WcT[(j+3) * KK + k], s_q[g][j+3], a3);
            }
            a0 = fmaf(s_WcT[48 * KK + k], s_q[g][48], a0);
            a1 = fmaf(s_WcT[49 * KK + k], s_q[g][49], a1);
            float acc = (a0 + a1) + (a2 + a3);
            float e = __expf(2.f * acc);
            s_ck[g][k] = 1.f - 2.f / (e + 1.f);       // tanh
        }
        __syncthreads();

        if (lt < MM) {                      // logits[m]
            const int m = lt;
            float a0 = 0.f, a1 = 0.f, a2 = 0.f, a3 = 0.f;
            #pragma unroll
            for (int k = 0; k < 48; k += 4) {
                a0 = fmaf(s_kmT[(k+0) * MM + m], s_ck[g][k+0], a0);
                a1 = fmaf(s_kmT[(k+1) * MM + m], s_ck[g][k+1], a1);
                a2 = fmaf(s_kmT[(k+2) * MM + m], s_ck[g][k+2], a2);
                a3 = fmaf(s_kmT[(k+3) * MM + m], s_ck[g][k+3], a3);
            }
            a0 = fmaf(s_kmT[48 * MM + m], s_ck[g][48], a0);
            a1 = fmaf(s_kmT[49 * MM + m], s_ck[g][49], a1);
            s_lg[g][m] = (a0 + a1) + (a2 + a3);
        }
        __syncthreads();

        if (lt < 32) {                      // softmax (warp 0 of group)
            float x0 = s_lg[g][lane];
            float x1 = (lane + 32 < MM) ? s_lg[g][lane + 32] : -INFINITY;
            float mx = fmaxf(x0, x1);
            #pragma unroll
            for (int o = 16; o > 0; o >>= 1)
                mx = fmaxf(mx, __shfl_xor_sync(0xffffffffu, mx, o));
            float e0 = __expf(x0 - mx);
            float e1 = (lane + 32 < MM) ? __expf(x1 - mx) : 0.f;
            float s = e0 + e1;
            #pragma unroll
            for (int o = 16; o > 0; o >>= 1)
                s += __shfl_xor_sync(0xffffffffu, s, o);
            float inv = 1.f / s;
            out[OUT_W + (size_t)p * MM + lane] = e0 * inv;
            if (lane + 32 < MM)
                out[OUT_W + (size_t)p * MM + lane + 32] = e1 * inv;
        }
        __syncthreads();
    }
}

// ============================================================================
// Kernel 2: the recurrence. Memory state in registers (thread owns (b,v)),
// w streamed from the precomputed output region, 3 barriers per step.
// ============================================================================

__device__ __forceinline__ float reduce4(float a0, float a1, float a2, float a3,
                                         int lane)
{
    if (lane & 16) { float t = a0; a0 = a2; a2 = t; t = a1; a1 = a3; a3 = t; }
    a0 += __shfl_xor_sync(0xffffffffu, a2, 16);
    a1 += __shfl_xor_sync(0xffffffffu, a3, 16);
    if (lane & 8)  { float t = a0; a0 = a1; a1 = t; }
    a0 += __shfl_xor_sync(0xffffffffu, a1, 8);
    a0 += __shfl_xor_sync(0xffffffffu, a0, 4);
    a0 += __shfl_xor_sync(0xffffffffu, a0, 2);
    a0 += __shfl_xor_sync(0xffffffffu, a0, 1);
    return a0;
}

__device__ __forceinline__ float dot4(float4 a, float4 b, float acc)
{
    acc = fmaf(a.x, b.x, acc);
    acc = fmaf(a.y, b.y, acc);
    acc = fmaf(a.z, b.z, acc);
    acc = fmaf(a.w, b.w, acc);
    return acc;
}

__global__ __launch_bounds__(NTHR, 1)
void agm_recur_kernel(const float* __restrict__ att,     // (B,S,A)
                      const float* __restrict__ vmem,    // (B,M,V)
                      const float* __restrict__ Wr,      // (A,V)
                      const float* __restrict__ br,      // (A)
                      const float* __restrict__ We,      // (V,2A)
                      const float* __restrict__ be,      // (V)
                      const float* __restrict__ Wa,      // (V,2A)
                      const float* __restrict__ ba,      // (V)
                      float* __restrict__ out)
{
    extern __shared__ float sh[];

    const int tid  = threadIdx.x;
    const int lane = tid & 31;
    const int wid  = tid >> 5;
    const int gb0  = blockIdx.x * NB;

    const int bcol = tid / VV;       // owned batch (0..3)
    const int vcol = tid % VV;       // owned memory column

    // ---- per-thread memory state ----
    float mem[MM];
    {
        const float* src = vmem + (size_t)(gb0 + bcol) * (MM * VV) + vcol;
        #pragma unroll
        for (int m = 0; m < MM; ++m) mem[m] = src[m * VV];
    }

    // ---- one-time setup ----
    for (int p = tid; p < VV * TWOA / 4; p += NTHR)        // We -> smem (float4)
        ((float4*)(sh + OFF_WE))[p] = ((const float4*)We)[p];
    for (int p = tid; p < AA * VV; p += NTHR) {            // Wr padded rows (52 f4)
        int a = p / VV, v = p % VV;
        sh[OFF_WR + a * 208 + v] = Wr[p];
    }
    for (int p = tid; p < AA; p += NTHR) sh[OFF_BR + p] = br[p];
    for (int p = tid; p < VV; p += NTHR) { sh[OFF_BE + p] = be[p]; sh[OFF_BA + p] = ba[p]; }
    // w(0), att(0)
    if (tid < NB * KK) {
        int b = tid / KK, m = tid % KK;
        sh[OFF_W + b * 52 + m] = out[OUT_W + ((size_t)(gb0 + b) * SS) * MM + m];
    } else if (tid < NB * KK + NB * AA) {
        int i = tid - NB * KK;
        sh[OFF_AT + i] = att[((size_t)(gb0 + (i >> 6)) * SS) * AA + (i & 63)];
    }
    __syncthreads();

    for (int t = 0; t < SS; ++t) {
        const int cur = t & 1, nxt = cur ^ 1;
        const int tp = (t + 1 < SS) ? t + 1 : SS - 1;

        // ---- prefetch issue for t+1 ----
        float pf = 0.f;
        if (tid < NB * KK) {
            pf = out[OUT_W + ((size_t)(gb0 + tid / KK) * SS + tp) * MM + tid % KK];
        } else if (tid < NB * KK + NB * AA) {
            int i = tid - NB * KK;
            pf = att[((size_t)(gb0 + (i >> 6)) * SS + tp) * AA + (i & 63)];
        }

        // ---- E: r[b][v] = sum_m w[b][m] * mem[m] ----
        {
            const float4* w4 = (const float4*)(sh + OFF_W) + (cur * NB + bcol) * 13;
            float a0 = 0.f, a1 = 0.f, a2 = 0.f, a3 = 0.f;
            #pragma unroll
            for (int i = 0; i < 12; i += 4) {
                float4 w0 = w4[i], w1 = w4[i+1], w2 = w4[i+2], w3 = w4[i+3];
                a0 = fmaf(w0.x, mem[4*i+0],  a0); a0 = fmaf(w0.y, mem[4*i+1],  a0);
                a0 = fmaf(w0.z, mem[4*i+2],  a0); a0 = fmaf(w0.w, mem[4*i+3],  a0);
                a1 = fmaf(w1.x, mem[4*i+4],  a1); a1 = fmaf(w1.y, mem[4*i+5],  a1);
                a1 = fmaf(w1.z, mem[4*i+6],  a1); a1 = fmaf(w1.w, mem[4*i+7],  a1);
                a2 = fmaf(w2.x, mem[4*i+8],  a2); a2 = fmaf(w2.y, mem[4*i+9],  a2);
                a2 = fmaf(w2.z, mem[4*i+10], a2); a2 = fmaf(w2.w, mem[4*i+11], a2);
                a3 = fmaf(w3.x, mem[4*i+12], a3); a3 = fmaf(w3.y, mem[4*i+13], a3);
                a3 = fmaf(w3.z, mem[4*i+14], a3); a3 = fmaf(w3.w, mem[4*i+15], a3);
            }
            float4 wl = w4[12];
            a0 = fmaf(wl.x, mem[48], a0);
            a1 = fmaf(wl.y, mem[49], a1);
            sh[OFF_R + bcol * VV + vcol] = (a0 + a1) + (a2 + a3);
        }
        __syncthreads();   // bar1

        // ---- F: rc[b][a] = r[b] . Wr[a] + br[a] (warp per row, Wr in smem) ----
        for (int a = wid; a < AA; a += 25) {
            const float4* wr4 = (const float4*)(sh + OFF_WR + a * 208);
            bool l2 = (lane < 18);
            float4 x = wr4[lane];
            float4 y = l2 ? wr4[32 + lane] : make_float4(0, 0, 0, 0);
            float acc[NB];
            #pragma unroll
            for (int b = 0; b < NB; ++b) {
                const float4* r4 = (const float4*)(sh + OFF_R + b * VV);
                float4 ra = r4[lane];
                float4 rb = l2 ? r4[32 + lane] : make_float4(0, 0, 0, 0);
                acc[b] = dot4(y, rb, dot4(x, ra, 0.f));
            }
            float s4 = reduce4(acc[0], acc[1], acc[2], acc[3], lane);
            if (!(lane & 7)) {
                int b = lane >> 3;
                sh[OFF_RC + b * AA + a] = s4 + sh[OFF_BR + a];
            }
        }
        __syncthreads();   // bar2

        // ---- rc output write + prefetch store (overlap with gates) ----
        if (tid < NB * AA) {
            out[OUT_RC + ((size_t)(gb0 + (tid >> 6)) * SS + t) * AA + (tid & 63)]
                = sh[OFF_RC + tid];
        }
        if (tid < NB * KK) {
            sh[OFF_W + (nxt * NB + tid / KK) * 52 + tid % KK] = pf;
        } else if (tid < NB * KK + NB * AA) {
            sh[OFF_AT + nxt * (NB * AA) + (tid - NB * KK)] = pf;
        }

        // ---- G: gate matvecs (warp-per-row; We from smem, Wa from gmem) ----
        if (t < SS - 1) {
            float4 wi0, wi1, wi2, wi3;
            {
                const float4* at4 = (const float4*)(sh + OFF_AT + cur * (NB * AA));
                const float4* rc4 = (const float4*)(sh + OFF_RC);
                int lo = lane & 15;
                wi0 = (lane < 16) ? at4[0 * 16 + lo] : rc4[0 * 16 + lo];
                wi1 = (lane < 16) ? at4[1 * 16 + lo] : rc4[1 * 16 + lo];
                wi2 = (lane < 16) ? at4[2 * 16 + lo] : rc4[2 * 16 + lo];
                wi3 = (lane < 16) ? at4[3 * 16 + lo] : rc4[3 * 16 + lo];
            }
            // pass 1: erase dots (We, smem)
            #pragma unroll
            for (int r8 = 0; r8 < 8; ++r8) {
                int v = wid + 25 * r8;
                float4 wv = ((const float4*)(sh + OFF_WE + v * TWOA))[lane];
                float a0 = dot4(wv, wi0, 0.f);
                float a1 = dot4(wv, wi1, 0.f);
                float a2 = dot4(wv, wi2, 0.f);
                float a3 = dot4(wv, wi3, 0.f);
                float s4 = reduce4(a0, a1, a2, a3, lane);
                if (!(lane & 7)) sh[OFF_ER + (lane >> 3) * VV + v] = s4;
            }
            // pass 2: add dots (Wa, gmem -> L1/L2)
            #pragma unroll
            for (int r8 = 0; r8 < 8; ++r8) {
                int v = wid + 25 * r8;
                float4 wv = ((const float4*)(Wa + v * TWOA))[lane];
                float a0 = dot4(wv, wi0, 0.f);
                float a1 = dot4(wv, wi1, 0.f);
                float a2 = dot4(wv, wi2, 0.f);
                float a3 = dot4(wv, wi3, 0.f);
                float s4 = reduce4(a0, a1, a2, a3, lane);
                if (!(lane & 7)) sh[OFF_AR + (lane >> 3) * VV + v] = s4;
            }
        }
        __syncthreads();   // bar3

        // ---- H: nonlinearities + in-register memory update ----
        if (t < SS - 1) {
            float re = sh[OFF_ER + bcol * VV + vcol] + sh[OFF_BE + vcol];
            float ra = sh[OFF_AR + bcol * VV + vcol] + sh[OFF_BA + vcol];
            float er = 1.f / (1.f + __expf(-re));          // sigmoid
            float ea = __expf(2.f * ra);
            float ad = 1.f - 2.f / (ea + 1.f);             // tanh

            const float4* w4 = (const float4*)(sh + OFF_W) + (cur * NB + bcol) * 13;
            #pragma unroll
            for (int i = 0; i < 12; ++i) {
                float4 ww = w4[i];
                mem[4*i+0] = fmaf(ww.x, fmaf(-er, mem[4*i+0], ad), mem[4*i+0]);
                mem[4*i+1] = fmaf(ww.y, fmaf(-er, mem[4*i+1], ad), mem[4*i+1]);
                mem[4*i+2] = fmaf(ww.z, fmaf(-er, mem[4*i+2], ad), mem[4*i+2]);
                mem[4*i+3] = fmaf(ww.w, fmaf(-er, mem[4*i+3], ad), mem[4*i+3]);
            }
            float4 wl = w4[12];
            mem[48] = fmaf(wl.x, fmaf(-er, mem[48], ad), mem[48]);
            mem[49] = fmaf(wl.y, fmaf(-er, mem[49], ad), mem[49]);
        }
        // no barrier: next E uses own regs + s_w[nxt] (written before bar3)
    }

    // ---- final memory state ----
    {
        float* dst = out + OUT_MEM + (size_t)(gb0 + bcol) * (MM * VV) + vcol;
        #pragma unroll
        for (int m = 0; m < MM; ++m) dst[m * VV] = mem[m];
    }
}

extern "C" void kernel_launch(void* const* d_in, const int* in_sizes, int n_in,
                              void* d_out, int out_size)
{
    (void)in_sizes; (void)n_in; (void)out_size;
    const float* q_emb = (const float*)d_in[0];
    const float* att   = (const float*)d_in[1];
    const float* vmem  = (const float*)d_in[2];
    const float* km    = (const float*)d_in[3];
    const float* Wc    = (const float*)d_in[4];
    const float* bc    = (const float*)d_in[5];
    const float* Wr    = (const float*)d_in[6];
    const float* br    = (const float*)d_in[7];
    const float* We    = (const float*)d_in[8];
    const float* be    = (const float*)d_in[9];
    const float* Wa    = (const float*)d_in[10];
    const float* ba    = (const float*)d_in[11];
    float* out = (float*)d_out;

    cudaFuncSetAttribute(agm_recur_kernel,
                         cudaFuncAttributeMaxDynamicSharedMemorySize,
                         SMEM2_BYTES);

    agm_weights_kernel<<<K1_GRID, K1_THREADS>>>(q_emb, km, Wc, bc, out);
    agm_recur_kernel<<<NBLK, NTHR, SMEM2_BYTES>>>(att, vmem, Wr, br,
                                                  We, be, Wa, ba, out);
}

// round 8
// speedup vs baseline: 1.1555x; 1.0490x over previous
#include <cuda_runtime.h>
#include <math.h>

#define BB   512
#define SS   1024
#define KK   50
#define MM   50
#define VV   200
#define AA   64
#define TWOA 128
#define NB   4
#define NBLK (BB / NB)     // 128 CTAs
#define NTHR 800           // 25 warps

// ---- kernel2 dynamic shared layout (float offsets, all 16B aligned) ----
#define OFF_WE  0                        // 200*128 = 25600 (We rows)
#define OFF_WR  (OFF_WE + VV*TWOA)       // 64*208 = 13312 (Wr rows padded)
#define OFF_W   (OFF_WR + AA*208)        // 2*4*52 double-buffered w
#define OFF_AT  (OFF_W  + 2*NB*52)       // 2*256 double-buffered att
#define OFF_RC  (OFF_AT + 2*NB*AA)       // 256
#define OFF_R   (OFF_RC + NB*AA)         // 800
#define OFF_ER  (OFF_R  + NB*VV)         // 800
#define OFF_AR  (OFF_ER + NB*VV)         // 800
#define OFF_BR  (OFF_AR + NB*VV)         // 64
#define OFF_BE  (OFF_BR + AA)            // 200
#define OFF_BA  (OFF_BE + VV)            // 200
#define SMEM2_FLOATS (OFF_BA + VV)
#define SMEM2_BYTES  (SMEM2_FLOATS * 4)  // ~171.8 KB

// Output offsets (floats) in concatenated flat output
#define OUT_RC  0ULL                                        // (B,S,A)
#define OUT_MEM ((unsigned long long)BB * SS * AA)          // (B,M,V)
#define OUT_W   (OUT_MEM + (unsigned long long)BB*MM*VV)    // (B,S,M)

// ============================================================================
// Kernel 1: precompute w[b,t,:] = softmax(tanh(q@Wc^T+bc)@km^T) for all (b,t).
// 8 independent 64-thread groups per block, synced with NAMED barriers so
// groups never serialize each other.
// ============================================================================
#define K1_GROUPS 8
#define K1_THREADS 512
#define K1_ITERS  16
#define K1_GRID   ((BB * SS) / (K1_GROUPS * K1_ITERS))   // 4096

#define GROUP_BAR(g) asm volatile("bar.sync %0, 64;" :: "r"((g) + 1) : "memory")

__global__ __launch_bounds__(K1_THREADS)
void agm_weights_kernel(const float* __restrict__ q_emb,  // (B,S,K)
                        const float* __restrict__ km,     // (M,K)
                        const float* __restrict__ Wc,     // (K,K)
                        const float* __restrict__ bc,     // (K)
                        float* __restrict__ out)
{
    __shared__ float s_WcT[KK * KK];   // [j][k]
    __shared__ float s_kmT[KK * MM];   // [k][m]
    __shared__ float s_bc[KK];
    __shared__ float s_q [K1_GROUPS][52];
    __shared__ float s_ck[K1_GROUPS][52];
    __shared__ float s_lg[K1_GROUPS][52];

    const int tid = threadIdx.x;
    const int g   = tid >> 6;
    const int lt  = tid & 63;
    const int lane = tid & 31;

    for (int p = tid; p < KK * KK; p += K1_THREADS) {
        int j = p / KK, k = p % KK;
        s_WcT[j * KK + k] = Wc[k * KK + j];
    }
    for (int p = tid; p < MM * KK; p += K1_THREADS) {
        int k = p / MM, m = p % MM;
        s_kmT[k * MM + m] = km[m * KK + k];
    }
    for (int p = tid; p < KK; p += K1_THREADS) s_bc[p] = bc[p];
    __syncthreads();

    for (int it = 0; it < K1_ITERS; ++it) {
        const int p = (blockIdx.x * K1_ITERS + it) * K1_GROUPS + g;  // b*SS+t

        if (lt < KK) s_q[g][lt] = q_emb[(size_t)p * KK + lt];
        GROUP_BAR(g);

        if (lt < KK) {                      // ck[k]
            const int k = lt;
            float a0 = s_bc[k], a1 = 0.f, a2 = 0.f, a3 = 0.f;
            #pragma unroll
            for (int j = 0; j < 48; j += 4) {
                a0 = fmaf(s_WcT[(j+0) * KK + k], s_q[g][j+0], a0);
                a1 = fmaf(s_WcT[(j+1) * KK + k], s_q[g][j+1], a1);
                a2 = fmaf(s_WcT[(j+2) * KK + k], s_q[g][j+2], a2);
                a3 = fmaf(s_WcT[(j+3) * KK + k], s_q[g][j+3], a3);
            }
            a0 = fmaf(s_WcT[48 * KK + k], s_q[g][48], a0);
            a1 = fmaf(s_WcT[49 * KK + k], s_q[g][49], a1);
            float acc = (a0 + a1) + (a2 + a3);
            float e = __expf(2.f * acc);
            s_ck[g][k] = 1.f - 2.f / (e + 1.f);       // tanh
        }
        GROUP_BAR(g);

        if (lt < MM) {                      // logits[m]
            const int m = lt;
            float a0 = 0.f, a1 = 0.f, a2 = 0.f, a3 = 0.f;
            #pragma unroll
            for (int k = 0; k < 48; k += 4) {
                a0 = fmaf(s_kmT[(k+0) * MM + m], s_ck[g][k+0], a0);
                a1 = fmaf(s_kmT[(k+1) * MM + m], s_ck[g][k+1], a1);
                a2 = fmaf(s_kmT[(k+2) * MM + m], s_ck[g][k+2], a2);
                a3 = fmaf(s_kmT[(k+3) * MM + m], s_ck[g][k+3], a3);
            }
            a0 = fmaf(s_kmT[48 * MM + m], s_ck[g][48], a0);
            a1 = fmaf(s_kmT[49 * MM + m], s_ck[g][49], a1);
            s_lg[g][m] = (a0 + a1) + (a2 + a3);
        }
        GROUP_BAR(g);

        if (lt < 32) {                      // softmax (warp 0 of group)
            float x0 = s_lg[g][lane];
            float x1 = (lane + 32 < MM) ? s_lg[g][lane + 32] : -INFINITY;
            float mx = fmaxf(x0, x1);
            #pragma unroll
            for (int o = 16; o > 0; o >>= 1)
                mx = fmaxf(mx, __shfl_xor_sync(0xffffffffu, mx, o));
            float e0 = __expf(x0 - mx);
            float e1 = (lane + 32 < MM) ? __expf(x1 - mx) : 0.f;
            float s = e0 + e1;
            #pragma unroll
            for (int o = 16; o > 0; o >>= 1)
                s += __shfl_xor_sync(0xffffffffu, s, o);
            float inv = 1.f / s;
            out[OUT_W + (size_t)p * MM + lane] = e0 * inv;
            if (lane + 32 < MM)
                out[OUT_W + (size_t)p * MM + lane + 32] = e1 * inv;
        }
        GROUP_BAR(g);
    }
}

// ============================================================================
// Kernel 2: recurrence, memory state in registers, fused update+read phase.
// ============================================================================

__device__ __forceinline__ float reduce4(float a0, float a1, float a2, float a3,
                                         int lane)
{
    if (lane & 16) { float t = a0; a0 = a2; a2 = t; t = a1; a1 = a3; a3 = t; }
    a0 += __shfl_xor_sync(0xffffffffu, a2, 16);
    a1 += __shfl_xor_sync(0xffffffffu, a3, 16);
    if (lane & 8)  { float t = a0; a0 = a1; a1 = t; }
    a0 += __shfl_xor_sync(0xffffffffu, a1, 8);
    a0 += __shfl_xor_sync(0xffffffffu, a0, 4);
    a0 += __shfl_xor_sync(0xffffffffu, a0, 2);
    a0 += __shfl_xor_sync(0xffffffffu, a0, 1);
    return a0;
}

__device__ __forceinline__ float dot4(float4 a, float4 b, float acc)
{
    acc = fmaf(a.x, b.x, acc);
    acc = fmaf(a.y, b.y, acc);
    acc = fmaf(a.z, b.z, acc);
    acc = fmaf(a.w, b.w, acc);
    return acc;
}

__global__ __launch_bounds__(NTHR)
void agm_recur_kernel(const float* __restrict__ att,     // (B,S,A)
                      const float* __restrict__ vmem,    // (B,M,V)
                      const float* __restrict__ Wr,      // (A,V)
                      const float* __restrict__ br,      // (A)
                      const float* __restrict__ We,      // (V,2A)
                      const float* __restrict__ be,      // (V)
                      const float* __restrict__ Wa,      // (V,2A)
                      const float* __restrict__ ba,      // (V)
                      float* __restrict__ out)
{
    extern __shared__ float sh[];

    const int tid  = threadIdx.x;
    const int lane = tid & 31;
    const int wid  = tid >> 5;
    const int gb0  = blockIdx.x * NB;

    const int bcol = tid / VV;
    const int vcol = tid % VV;

    // ---- per-thread memory state ----
    float mem[MM];
    {
        const float* src = vmem + (size_t)(gb0 + bcol) * (MM * VV) + vcol;
        #pragma unroll
        for (int m = 0; m < MM; ++m) mem[m] = src[m * VV];
    }

    // ---- one-time setup ----
    for (int p = tid; p < VV * TWOA / 4; p += NTHR)
        ((float4*)(sh + OFF_WE))[p] = ((const float4*)We)[p];
    for (int p = tid; p < AA * VV; p += NTHR) {
        int a = p / VV, v = p % VV;
        sh[OFF_WR + a * 208 + v] = Wr[p];
    }
    for (int p = tid; p < AA; p += NTHR) sh[OFF_BR + p] = br[p];
    for (int p = tid; p < VV; p += NTHR) { sh[OFF_BE + p] = be[p]; sh[OFF_BA + p] = ba[p]; }
    if (tid < NB * KK) {              // w(0) into buffer 0
        int b = tid / KK, m = tid % KK;
        sh[OFF_W + b * 52 + m] = out[OUT_W + ((size_t)(gb0 + b) * SS) * MM + m];
    } else if (tid < NB * KK + NB * AA) {  // att(0) into buffer 0
        int i = tid - NB * KK;
        sh[OFF_AT + i] = att[((size_t)(gb0 + (i >> 6)) * SS) * AA + (i & 63)];
    }
    __syncthreads();

    // ---- prologue: r(0) = w(0) . mem ----
    {
        const float4* w4 = (const float4*)(sh + OFF_W) + bcol * 13;
        float a0 = 0.f, a1 = 0.f, a2 = 0.f, a3 = 0.f;
        #pragma unroll
        for (int i = 0; i < 12; i += 4) {
            float4 w0 = w4[i], w1 = w4[i+1], w2 = w4[i+2], w3 = w4[i+3];
            a0 = fmaf(w0.x, mem[4*i+0],  a0); a0 = fmaf(w0.y, mem[4*i+1],  a0);
            a0 = fmaf(w0.z, mem[4*i+2],  a0); a0 = fmaf(w0.w, mem[4*i+3],  a0);
            a1 = fmaf(w1.x, mem[4*i+4],  a1); a1 = fmaf(w1.y, mem[4*i+5],  a1);
            a1 = fmaf(w1.z, mem[4*i+6],  a1); a1 = fmaf(w1.w, mem[4*i+7],  a1);
            a2 = fmaf(w2.x, mem[4*i+8],  a2); a2 = fmaf(w2.y, mem[4*i+9],  a2);
            a2 = fmaf(w2.z, mem[4*i+10], a2); a2 = fmaf(w2.w, mem[4*i+11], a2);
            a3 = fmaf(w3.x, mem[4*i+12], a3); a3 = fmaf(w3.y, mem[4*i+13], a3);
            a3 = fmaf(w3.z, mem[4*i+14], a3); a3 = fmaf(w3.w, mem[4*i+15], a3);
        }
        float4 wl = w4[12];
        a0 = fmaf(wl.x, mem[48], a0);
        a1 = fmaf(wl.y, mem[49], a1);
        sh[OFF_R + bcol * VV + vcol] = (a0 + a1) + (a2 + a3);
    }
    __syncthreads();

    for (int t = 0; t < SS; ++t) {
        const int cur = t & 1, nxt = cur ^ 1;
        const int tp = (t + 1 < SS) ? t + 1 : SS - 1;
        const bool last = (t == SS - 1);

        // ---- prefetch issue for t+1 ----
        float pf = 0.f;
        if (tid < NB * KK) {
            pf = out[OUT_W + ((size_t)(gb0 + tid / KK) * SS + tp) * MM + tid % KK];
        } else if (tid < NB * KK + NB * AA) {
            int i = tid - NB * KK;
            pf = att[((size_t)(gb0 + (i >> 6)) * SS + tp) * AA + (i & 63)];
        }

        // ---- F: rc[b][a] = r[b] . Wr[a] + br[a] ----
        for (int a = wid; a < AA; a += 25) {
            const float4* wr4 = (const float4*)(sh + OFF_WR + a * 208);
            bool l2 = (lane < 18);
            float4 x = wr4[lane];
            float4 y = l2 ? wr4[32 + lane] : make_float4(0, 0, 0, 0);
            float acc[NB];
            #pragma unroll
            for (int b = 0; b < NB; ++b) {
                const float4* r4 = (const float4*)(sh + OFF_R + b * VV);
                float4 ra = r4[lane];
                float4 rb = l2 ? r4[32 + lane] : make_float4(0, 0, 0, 0);
                acc[b] = dot4(y, rb, dot4(x, ra, 0.f));
            }
            float s4 = reduce4(acc[0], acc[1], acc[2], acc[3], lane);
            if (!(lane & 7)) {
                int b = lane >> 3;
                sh[OFF_RC + b * AA + a] = s4 + sh[OFF_BR + a];
            }
        }
        __syncthreads();   // bar A

        // ---- rc out-store + prefetch stores (overlap with gates) ----
        if (tid < NB * AA) {
            out[OUT_RC + ((size_t)(gb0 + (tid >> 6)) * SS + t) * AA + (tid & 63)]
                = sh[OFF_RC + tid];
        }
        if (last) break;   // nothing further on the final step

        if (tid < NB * KK) {
            sh[OFF_W + (nxt * NB + tid / KK) * 52 + tid % KK] = pf;
        } else if (tid < NB * KK + NB * AA) {
            sh[OFF_AT + nxt * (NB * AA) + (tid - NB * KK)] = pf;
        }

        // ---- G: gate matvecs (warp-per-row) ----
        {
            float4 wi0, wi1, wi2, wi3;
            {
                const float4* at4 = (const float4*)(sh + OFF_AT + cur * (NB * AA));
                const float4* rc4 = (const float4*)(sh + OFF_RC);
                int lo = lane & 15;
                wi0 = (lane < 16) ? at4[0 * 16 + lo] : rc4[0 * 16 + lo];
                wi1 = (lane < 16) ? at4[1 * 16 + lo] : rc4[1 * 16 + lo];
                wi2 = (lane < 16) ? at4[2 * 16 + lo] : rc4[2 * 16 + lo];
                wi3 = (lane < 16) ? at4[3 * 16 + lo] : rc4[3 * 16 + lo];
            }
            // pass 1: erase dots (We, smem)
            #pragma unroll
            for (int r8 = 0; r8 < 8; ++r8) {
                int v = wid + 25 * r8;
                float4 wv = ((const float4*)(sh + OFF_WE + v * TWOA))[lane];
                float a0 = dot4(wv, wi0, 0.f);
                float a1 = dot4(wv, wi1, 0.f);
                float a2 = dot4(wv, wi2, 0.f);
                float a3 = dot4(wv, wi3, 0.f);
                float s4 = reduce4(a0, a1, a2, a3, lane);
                if (!(lane & 7)) sh[OFF_ER + (lane >> 3) * VV + v] = s4;
            }
            // pass 2: add dots (Wa, gmem via L1)
            #pragma unroll
            for (int r8 = 0; r8 < 8; ++r8) {
                int v = wid + 25 * r8;
                float4 wv = ((const float4*)(Wa + v * TWOA))[lane];
                float a0 = dot4(wv, wi0, 0.f);
                float a1 = dot4(wv, wi1, 0.f);
                float a2 = dot4(wv, wi2, 0.f);
                float a3 = dot4(wv, wi3, 0.f);
                float s4 = reduce4(a0, a1, a2, a3, lane);
                if (!(lane & 7)) sh[OFF_AR + (lane >> 3) * VV + v] = s4;
            }
        }
        __syncthreads();   // bar B

        // ---- fused H+E: nonlinearity, mem update w(t), read r(t+1) w(t+1) ----
        {
            float re = sh[OFF_ER + bcol * VV + vcol] + sh[OFF_BE + vcol];
            float ra = sh[OFF_AR + bcol * VV + vcol] + sh[OFF_BA + vcol];
            float er = 1.f / (1.f + __expf(-re));          // sigmoid
            float ea = __expf(2.f * ra);
            float ad = 1.f - 2.f / (ea + 1.f);             // tanh

            const float4* wc4 = (const float4*)(sh + OFF_W) + (cur * NB + bcol) * 13;
            const float4* wn4 = (const float4*)(sh + OFF_W) + (nxt * NB + bcol) * 13;
            float a0 = 0.f, a1 = 0.f, a2 = 0.f, a3 = 0.f;
            #pragma unroll
            for (int i = 0; i < 12; ++i) {
                float4 wc = wc4[i];
                float4 wn = wn4[i];
                float m0 = mem[4*i+0], m1 = mem[4*i+1];
                float m2 = mem[4*i+2], m3 = mem[4*i+3];
                m0 = fmaf(wc.x, fmaf(-er, m0, ad), m0);
                m1 = fmaf(wc.y, fmaf(-er, m1, ad), m1);
                m2 = fmaf(wc.z, fmaf(-er, m2, ad), m2);
                m3 = fmaf(wc.w, fmaf(-er, m3, ad), m3);
                a0 = fmaf(wn.x, m0, a0);
                a1 = fmaf(wn.y, m1, a1);
                a2 = fmaf(wn.z, m2, a2);
                a3 = fmaf(wn.w, m3, a3);
                mem[4*i+0] = m0; mem[4*i+1] = m1;
                mem[4*i+2] = m2; mem[4*i+3] = m3;
            }
            float4 wcl = wc4[12];
            float4 wnl = wn4[12];
            float m0 = mem[48], m1 = mem[49];
            m0 = fmaf(wcl.x, fmaf(-er, m0, ad), m0);
            m1 = fmaf(wcl.y, fmaf(-er, m1, ad), m1);
            a0 = fmaf(wnl.x, m0, a0);
            a1 = fmaf(wnl.y, m1, a1);
            mem[48] = m0; mem[49] = m1;
            sh[OFF_R + bcol * VV + vcol] = (a0 + a1) + (a2 + a3);
        }
        __syncthreads();   // bar C
    }

    // ---- final memory state ----
    {
        float* dst = out + OUT_MEM + (size_t)(gb0 + bcol) * (MM * VV) + vcol;
        #pragma unroll
        for (int m = 0; m < MM; ++m) dst[m * VV] = mem[m];
    }
}

extern "C" void kernel_launch(void* const* d_in, const int* in_sizes, int n_in,
                              void* d_out, int out_size)
{
    (void)in_sizes; (void)n_in; (void)out_size;
    const float* q_emb = (const float*)d_in[0];
    const float* att   = (const float*)d_in[1];
    const float* vmem  = (const float*)d_in[2];
    const float* km    = (const float*)d_in[3];
    const float* Wc    = (const float*)d_in[4];
    const float* bc    = (const float*)d_in[5];
    const float* Wr    = (const float*)d_in[6];
    const float* br    = (const float*)d_in[7];
    const float* We    = (const float*)d_in[8];
    const float* be    = (const float*)d_in[9];
    const float* Wa    = (const float*)d_in[10];
    const float* ba    = (const float*)d_in[11];
    float* out = (float*)d_out;

    cudaFuncSetAttribute(agm_recur_kernel,
                         cudaFuncAttributeMaxDynamicSharedMemorySize,
                         SMEM2_BYTES);

    agm_weights_kernel<<<K1_GRID, K1_THREADS>>>(q_emb, km, Wc, bc, out);
    agm_recur_kernel<<<NBLK, NTHR, SMEM2_BYTES>>>(att, vmem, Wr, br,
                                                  We, be, Wa, ba, out);
}

// round 9
// speedup vs baseline: 1.2402x; 1.0734x over previous
#include <cuda_runtime.h>
#include <math.h>

#define BB   512
#define SS   1024
#define KK   50
#define MM   50
#define VV   200
#define AA   64
#define TWOA 128
#define NB   4
#define NBLK (BB / NB)     // 128 CTAs
#define NTHR 800           // 25 warps

// ---- kernel2 dynamic shared layout (float offsets, all 16B aligned) ----
#define OFF_WE  0                        // 200*128 = 25600 (We rows)
#define OFF_WR  (OFF_WE + VV*TWOA)       // 64*208 = 13312 (Wr rows padded)
#define OFF_W   (OFF_WR + AA*208)        // 2*4*52 double-buffered w
#define OFF_AT  (OFF_W  + 2*NB*52)       // 2*256 double-buffered att
#define OFF_RC  (OFF_AT + 2*NB*AA)       // 256
#define OFF_R   (OFF_RC + NB*AA)         // 800
#define OFF_ER  (OFF_R  + NB*VV)         // 800
#define OFF_AR  (OFF_ER + NB*VV)         // 800
#define OFF_BR  (OFF_AR + NB*VV)         // 64
#define OFF_BE  (OFF_BR + AA)            // 200
#define OFF_BA  (OFF_BE + VV)            // 200
#define SMEM2_FLOATS (OFF_BA + VV)
#define SMEM2_BYTES  (SMEM2_FLOATS * 4)  // ~171.8 KB

// Output offsets (floats) in concatenated flat output
#define OUT_RC  0ULL                                        // (B,S,A)
#define OUT_MEM ((unsigned long long)BB * SS * AA)          // (B,M,V)
#define OUT_W   (OUT_MEM + (unsigned long long)BB*MM*VV)    // (B,S,M)

// ---- packed f32x2 helpers (sm_103a) ----
typedef unsigned long long u64;

__device__ __forceinline__ u64 pk2(float lo, float hi) {
    u64 d;
    asm("mov.b64 %0, {%1, %2};" : "=l"(d) : "f"(lo), "f"(hi));
    return d;
}
__device__ __forceinline__ float unlo(u64 v) {
    float f; asm("{ .reg .f32 t; mov.b64 {%0, t}, %1; }" : "=f"(f) : "l"(v)); return f;
}
__device__ __forceinline__ float unhi(u64 v) {
    float f; asm("{ .reg .f32 t; mov.b64 {t, %0}, %1; }" : "=f"(f) : "l"(v)); return f;
}
__device__ __forceinline__ u64 ffma2(u64 a, u64 b, u64 c) {
    u64 d;
    asm("fma.rn.f32x2 %0, %1, %2, %3;" : "=l"(d) : "l"(a), "l"(b), "l"(c));
    return d;
}
__device__ __forceinline__ u64 fadd2(u64 a, u64 b) {
    u64 d;
    asm("add.rn.f32x2 %0, %1, %2;" : "=l"(d) : "l"(a), "l"(b));
    return d;
}

union F4U2 { float4 f; u64 u[2]; };

// ============================================================================
// Kernel 1: w[b,t,:] = softmax(tanh(q@Wc^T+bc)@km^T) for all (b,t).
// One WARP per item; __syncwarp-only synchronization; logits/softmax in regs.
// ============================================================================
#define K1_THREADS 256
#define K1_ITERS   8
#define K1_GRID    ((BB * SS) / (8 * K1_ITERS))   // 8192

__global__ __launch_bounds__(K1_THREADS)
void agm_weights_kernel(const float* __restrict__ q_emb,  // (B,S,K)
                        const float* __restrict__ km,     // (M,K)
                        const float* __restrict__ Wc,     // (K,K)
                        const float* __restrict__ bc,     // (K)
                        float* __restrict__ out)
{
    __shared__ float s_WcT[KK * KK];   // [j][k]
    __shared__ float s_kmT[KK * MM];   // [k][m]
    __shared__ float s_bc[KK];
    __shared__ float s_q [8][52];
    __shared__ float s_ck[8][52];

    const int tid  = threadIdx.x;
    const int w    = tid >> 5;
    const int lane = tid & 31;

    for (int p = tid; p < KK * KK; p += K1_THREADS) {
        int j = p / KK, k = p % KK;
        s_WcT[j * KK + k] = Wc[k * KK + j];
    }
    for (int p = tid; p < MM * KK; p += K1_THREADS) {
        int k = p / MM, m = p % MM;
        s_kmT[k * MM + m] = km[m * KK + k];
    }
    for (int p = tid; p < KK; p += K1_THREADS) s_bc[p] = bc[p];
    __syncthreads();

    const bool two = (lane < KK - 32);   // lanes 0..17 handle a second element

    for (int it = 0; it < K1_ITERS; ++it) {
        const int p = (blockIdx.x * 8 + w) * K1_ITERS + it;   // item = b*SS+t

        if (lane < 25) {
            float2 v = ((const float2*)(q_emb + (size_t)p * KK))[lane];
            s_q[w][2 * lane]     = v.x;
            s_q[w][2 * lane + 1] = v.y;
        }
        __syncwarp();

        // ck = tanh(q @ Wc^T + bc)
        {
            float a1 = s_bc[lane];
            float a2 = two ? s_bc[lane + 32] : 0.f;
            #pragma unroll
            for (int j = 0; j < KK; ++j) {
                float qj = s_q[w][j];
                a1 = fmaf(s_WcT[j * KK + lane], qj, a1);
                if (two) a2 = fmaf(s_WcT[j * KK + lane + 32], qj, a2);
            }
            float e1 = __expf(2.f * a1);
            s_ck[w][lane] = 1.f - 2.f / (e1 + 1.f);
            if (two) {
                float e2 = __expf(2.f * a2);
                s_ck[w][lane + 32] = 1.f - 2.f / (e2 + 1.f);
            }
        }
        __syncwarp();

        // logits (kept in registers) + softmax
        float x0 = 0.f;
        float x1 = two ? 0.f : -INFINITY;
        #pragma unroll
        for (int k = 0; k < KK; ++k) {
            float ckv = s_ck[w][k];
            x0 = fmaf(s_kmT[k * MM + lane], ckv, x0);
            if (two) x1 = fmaf(s_kmT[k * MM + lane + 32], ckv, x1);
        }
        float mx = fmaxf(x0, x1);
        #pragma unroll
        for (int o = 16; o > 0; o >>= 1)
            mx = fmaxf(mx, __shfl_xor_sync(0xffffffffu, mx, o));
        float e0 = __expf(x0 - mx);
        float e1 = two ? __expf(x1 - mx) : 0.f;
        float s = e0 + e1;
        #pragma unroll
        for (int o = 16; o > 0; o >>= 1)
            s += __shfl_xor_sync(0xffffffffu, s, o);
        float inv = 1.f / s;
        out[OUT_W + (size_t)p * MM + lane] = e0 * inv;
        if (two) out[OUT_W + (size_t)p * MM + lane + 32] = e1 * inv;
        __syncwarp();
    }
}

// ============================================================================
// Kernel 2: recurrence. Memory state as 25 packed f32x2 pairs per thread.
// ============================================================================

__device__ __forceinline__ float reduce4(float a0, float a1, float a2, float a3,
                                         int lane)
{
    if (lane & 16) { float t = a0; a0 = a2; a2 = t; t = a1; a1 = a3; a3 = t; }
    a0 += __shfl_xor_sync(0xffffffffu, a2, 16);
    a1 += __shfl_xor_sync(0xffffffffu, a3, 16);
    if (lane & 8)  { float t = a0; a0 = a1; a1 = t; }
    a0 += __shfl_xor_sync(0xffffffffu, a1, 8);
    a0 += __shfl_xor_sync(0xffffffffu, a0, 4);
    a0 += __shfl_xor_sync(0xffffffffu, a0, 2);
    a0 += __shfl_xor_sync(0xffffffffu, a0, 1);
    return a0;
}

__device__ __forceinline__ float dot4(float4 a, float4 b, float acc)
{
    acc = fmaf(a.x, b.x, acc);
    acc = fmaf(a.y, b.y, acc);
    acc = fmaf(a.z, b.z, acc);
    acc = fmaf(a.w, b.w, acc);
    return acc;
}

__global__ __launch_bounds__(NTHR)
void agm_recur_kernel(const float* __restrict__ att,     // (B,S,A)
                      const float* __restrict__ vmem,    // (B,M,V)
                      const float* __restrict__ Wr,      // (A,V)
                      const float* __restrict__ br,      // (A)
                      const float* __restrict__ We,      // (V,2A)
                      const float* __restrict__ be,      // (V)
                      const float* __restrict__ Wa,      // (V,2A)
                      const float* __restrict__ ba,      // (V)
                      float* __restrict__ out)
{
    extern __shared__ float sh[];

    const int tid  = threadIdx.x;
    const int lane = tid & 31;
    const int wid  = tid >> 5;
    const int gb0  = blockIdx.x * NB;

    const int bcol = tid / VV;
    const int vcol = tid % VV;

    // ---- per-thread memory state: 25 packed pairs (m=2i, m=2i+1) ----
    u64 mem2[25];
    {
        const float* src = vmem + (size_t)(gb0 + bcol) * (MM * VV) + vcol;
        #pragma unroll
        for (int i = 0; i < 25; ++i)
            mem2[i] = pk2(src[(2 * i) * VV], src[(2 * i + 1) * VV]);
    }

    // ---- one-time setup ----
    for (int p = tid; p < VV * TWOA / 4; p += NTHR)
        ((float4*)(sh + OFF_WE))[p] = ((const float4*)We)[p];
    for (int p = tid; p < AA * VV; p += NTHR) {
        int a = p / VV, v = p % VV;
        sh[OFF_WR + a * 208 + v] = Wr[p];
    }
    for (int p = tid; p < AA; p += NTHR) sh[OFF_BR + p] = br[p];
    for (int p = tid; p < VV; p += NTHR) { sh[OFF_BE + p] = be[p]; sh[OFF_BA + p] = ba[p]; }
    if (tid < NB * KK) {              // w(0) into buffer 0
        int b = tid / KK, m = tid % KK;
        sh[OFF_W + b * 52 + m] = out[OUT_W + ((size_t)(gb0 + b) * SS) * MM + m];
    } else if (tid < NB * KK + NB * AA) {  // att(0) into buffer 0
        int i = tid - NB * KK;
        sh[OFF_AT + i] = att[((size_t)(gb0 + (i >> 6)) * SS) * AA + (i & 63)];
    }
    __syncthreads();

    // ---- prologue: r(0) = w(0) . mem ----
    {
        const float4* w4 = (const float4*)(sh + OFF_W) + bcol * 13;
        u64 a0 = 0, a1 = 0;
        #pragma unroll
        for (int i = 0; i < 12; ++i) {
            F4U2 ww; ww.f = w4[i];
            a0 = ffma2(ww.u[0], mem2[2 * i],     a0);
            a1 = ffma2(ww.u[1], mem2[2 * i + 1], a1);
        }
        F4U2 wl; wl.f = w4[12];
        a0 = ffma2(wl.u[0], mem2[24], a0);
        u64 s2 = fadd2(a0, a1);
        sh[OFF_R + bcol * VV + vcol] = unlo(s2) + unhi(s2);
    }
    __syncthreads();

    for (int t = 0; t < SS; ++t) {
        const int cur = t & 1, nxt = cur ^ 1;
        const int tp = (t + 1 < SS) ? t + 1 : SS - 1;
        const bool last = (t == SS - 1);

        // ---- prefetch issue for t+1 ----
        float pf = 0.f;
        if (tid < NB * KK) {
            pf = out[OUT_W + ((size_t)(gb0 + tid / KK) * SS + tp) * MM + tid % KK];
        } else if (tid < NB * KK + NB * AA) {
            int i = tid - NB * KK;
            pf = att[((size_t)(gb0 + (i >> 6)) * SS + tp) * AA + (i & 63)];
        }

        // ---- F: rc[b][a] = r[b] . Wr[a] + br[a] ----
        for (int a = wid; a < AA; a += 25) {
            const float4* wr4 = (const float4*)(sh + OFF_WR + a * 208);
            bool l2 = (lane < 18);
            float4 x = wr4[lane];
            float4 y = l2 ? wr4[32 + lane] : make_float4(0, 0, 0, 0);
            float acc[NB];
            #pragma unroll
            for (int b = 0; b < NB; ++b) {
                const float4* r4 = (const float4*)(sh + OFF_R + b * VV);
                float4 ra = r4[lane];
                float4 rb = l2 ? r4[32 + lane] : make_float4(0, 0, 0, 0);
                acc[b] = dot4(y, rb, dot4(x, ra, 0.f));
            }
            float s4 = reduce4(acc[0], acc[1], acc[2], acc[3], lane);
            if (!(lane & 7)) {
                int b = lane >> 3;
                sh[OFF_RC + b * AA + a] = s4 + sh[OFF_BR + a];
            }
        }
        __syncthreads();   // bar A

        // ---- rc out-store ----
        if (tid < NB * AA) {
            out[OUT_RC + ((size_t)(gb0 + (tid >> 6)) * SS + t) * AA + (tid & 63)]
                = sh[OFF_RC + tid];
        }
        if (last) break;

        // ---- prefetch stores (overlap with gates) ----
        if (tid < NB * KK) {
            sh[OFF_W + (nxt * NB + tid / KK) * 52 + tid % KK] = pf;
        } else if (tid < NB * KK + NB * AA) {
            sh[OFF_AT + nxt * (NB * AA) + (tid - NB * KK)] = pf;
        }

        // ---- G: merged gate matvecs (warp-per-row, We smem + Wa gmem) ----
        {
            float4 wi0, wi1, wi2, wi3;
            {
                const float4* at4 = (const float4*)(sh + OFF_AT + cur * (NB * AA));
                const float4* rc4 = (const float4*)(sh + OFF_RC);
                int lo = lane & 15;
                wi0 = (lane < 16) ? at4[0 * 16 + lo] : rc4[0 * 16 + lo];
                wi1 = (lane < 16) ? at4[1 * 16 + lo] : rc4[1 * 16 + lo];
                wi2 = (lane < 16) ? at4[2 * 16 + lo] : rc4[2 * 16 + lo];
                wi3 = (lane < 16) ? at4[3 * 16 + lo] : rc4[3 * 16 + lo];
            }
            #pragma unroll 4
            for (int r8 = 0; r8 < 8; ++r8) {
                int v = wid + 25 * r8;
                float4 wa = ((const float4*)(Wa + v * TWOA))[lane];   // LDG early
                float4 we = ((const float4*)(sh + OFF_WE + v * TWOA))[lane];
                float e0 = dot4(we, wi0, 0.f);
                float e1 = dot4(we, wi1, 0.f);
                float e2 = dot4(we, wi2, 0.f);
                float e3 = dot4(we, wi3, 0.f);
                float g0 = dot4(wa, wi0, 0.f);
                float g1 = dot4(wa, wi1, 0.f);
                float g2 = dot4(wa, wi2, 0.f);
                float g3 = dot4(wa, wi3, 0.f);
                float se = reduce4(e0, e1, e2, e3, lane);
                float sg = reduce4(g0, g1, g2, g3, lane);
                if (!(lane & 7)) {
                    sh[OFF_ER + (lane >> 3) * VV + v] = se;
                    sh[OFF_AR + (lane >> 3) * VV + v] = sg;
                }
            }
        }
        __syncthreads();   // bar B

        // ---- fused H+E (packed f32x2): update with w(t), read with w(t+1) ----
        {
            float re = sh[OFF_ER + bcol * VV + vcol] + sh[OFF_BE + vcol];
            float ra = sh[OFF_AR + bcol * VV + vcol] + sh[OFF_BA + vcol];
            float er = 1.f / (1.f + __expf(-re));          // sigmoid
            float ea = __expf(2.f * ra);
            float ad = 1.f - 2.f / (ea + 1.f);             // tanh

            u64 nEr2 = pk2(-er, -er);
            u64 ad2  = pk2(ad, ad);

            const float4* wc4 = (const float4*)(sh + OFF_W) + (cur * NB + bcol) * 13;
            const float4* wn4 = (const float4*)(sh + OFF_W) + (nxt * NB + bcol) * 13;
            u64 a0 = 0, a1 = 0;
            #pragma unroll
            for (int i = 0; i < 12; ++i) {
                F4U2 wc; wc.f = wc4[i];
                F4U2 wn; wn.f = wn4[i];
                u64 m0 = mem2[2 * i];
                u64 m1 = mem2[2 * i + 1];
                m0 = ffma2(wc.u[0], ffma2(nEr2, m0, ad2), m0);
                m1 = ffma2(wc.u[1], ffma2(nEr2, m1, ad2), m1);
                a0 = ffma2(wn.u[0], m0, a0);
                a1 = ffma2(wn.u[1], m1, a1);
                mem2[2 * i]     = m0;
                mem2[2 * i + 1] = m1;
            }
            F4U2 wcl; wcl.f = wc4[12];
            F4U2 wnl; wnl.f = wn4[12];
            u64 m = mem2[24];
            m = ffma2(wcl.u[0], ffma2(nEr2, m, ad2), m);
            a0 = ffma2(wnl.u[0], m, a0);
            mem2[24] = m;
            u64 s2 = fadd2(a0, a1);
            sh[OFF_R + bcol * VV + vcol] = unlo(s2) + unhi(s2);
        }
        __syncthreads();   // bar C
    }

    // ---- final memory state ----
    {
        float* dst = out + OUT_MEM + (size_t)(gb0 + bcol) * (MM * VV) + vcol;
        #pragma unroll
        for (int i = 0; i < 25; ++i) {
            dst[(2 * i) * VV]     = unlo(mem2[i]);
            dst[(2 * i + 1) * VV] = unhi(mem2[i]);
        }
    }
}

extern "C" void kernel_launch(void* const* d_in, const int* in_sizes, int n_in,
                              void* d_out, int out_size)
{
    (void)in_sizes; (void)n_in; (void)out_size;
    const float* q_emb = (const float*)d_in[0];
    const float* att   = (const float*)d_in[1];
    const float* vmem  = (const float*)d_in[2];
    const float* km    = (const float*)d_in[3];
    const float* Wc    = (const float*)d_in[4];
    const float* bc    = (const float*)d_in[5];
    const float* Wr    = (const float*)d_in[6];
    const float* br    = (const float*)d_in[7];
    const float* We    = (const float*)d_in[8];
    const float* be    = (const float*)d_in[9];
    const float* Wa    = (const float*)d_in[10];
    const float* ba    = (const float*)d_in[11];
    float* out = (float*)d_out;

    cudaFuncSetAttribute(agm_recur_kernel,
                         cudaFuncAttributeMaxDynamicSharedMemorySize,
                         SMEM2_BYTES);

    agm_weights_kernel<<<K1_GRID, K1_THREADS>>>(q_emb, km, Wc, bc, out);
    agm_recur_kernel<<<NBLK, NTHR, SMEM2_BYTES>>>(att, vmem, Wr, br,
                                                  We, be, Wa, ba, out);
}